// round 12
// baseline (speedup 1.0000x reference)
#include <cuda_runtime.h>
#include <cuda_fp16.h>
#include <cstdint>

// Problem shape (fixed by the dataset)
#define Bb 8
#define Ss 2048
#define Dd 768
#define Oo 768
constexpr float SCALE = 0.125f;  // 1/sqrt(64), hardcoded in reference

constexpr size_t N_X   = (size_t)Bb * Ss * Dd;
constexpr size_t N_W   = (size_t)3 * Dd * Oo;
constexpr size_t N_QKV = (size_t)Bb * Ss * Oo;
constexpr size_t N_SC  = (size_t)Bb * Ss * Ss;

// Scratch (static device globals — no runtime allocation)
__device__ __half g_x16[N_X];             // x fp16 [B*S, D]
__device__ __half g_w16[2 * Dd * Oo];     // Wq|Wk fp16 [D, O]
__device__ __half g_wTv[(size_t)Dd * Oo]; // Wv^T fp16 [O, D]
__device__ __half g_M2[(size_t)Dd * Dd];  // M2 = Wk @ Wq^T fp16
__device__ __half g_y[N_QKV];             // Y = X @ M2^T fp16
__device__ __half g_vT[N_QKV];            // V^T fp16 [B][O, S]
__device__ __half g_exp[N_SC];            // E = exp(scores) fp16 (unnormalized)
__device__ float  g_rsum[(size_t)Bb * Ss]; // rowsum(E) fp32 (atomic accum)

// ---------------------------------------------------------------------------
// PTX helpers (base sm_103 ISA: cp.async, ldmatrix, mma.sync)
// ---------------------------------------------------------------------------
__device__ __forceinline__ uint32_t smem_u32(const void* p) {
    return (uint32_t)__cvta_generic_to_shared(p);
}
__device__ __forceinline__ void cp16(uint32_t saddr, const void* gaddr) {
    asm volatile("cp.async.cg.shared.global [%0], [%1], 16;\n" :: "r"(saddr), "l"(gaddr));
}
__device__ __forceinline__ void cp_commit() {
    asm volatile("cp.async.commit_group;\n" ::: "memory");
}
__device__ __forceinline__ void cp_wait1() {
    asm volatile("cp.async.wait_group 1;\n" ::: "memory");
}

#define LDSM4(r0, r1, r2, r3, addr) \
    asm volatile("ldmatrix.sync.aligned.m8n8.x4.shared.b16 {%0,%1,%2,%3}, [%4];" \
                 : "=r"(r0), "=r"(r1), "=r"(r2), "=r"(r3) : "r"(addr))

#define MMA16816(d, a, b) \
    asm volatile("mma.sync.aligned.m16n8k16.row.col.f32.f16.f16.f32 " \
                 "{%0,%1,%2,%3},{%4,%5,%6,%7},{%8,%9},{%0,%1,%2,%3};" \
                 : "+f"((d)[0]), "+f"((d)[1]), "+f"((d)[2]), "+f"((d)[3]) \
                 : "r"((a)[0]), "r"((a)[1]), "r"((a)[2]), "r"((a)[3]), \
                   "r"((b)[0]), "r"((b)[1]))

// ---------------------------------------------------------------------------
// mma.sync GEMM (NT):  C[M,N] = scale * A[M,K] @ B[N,K]^T  (both K-major fp16)
// Round-8 proven geometry: block 128x128x64, 3-stage cp.async, 8 warps (2x4),
// warp tile 64x32, double-buffered fragments, 2 CTAs/SM.
// OMODE: 0 = fp32 out, divided by rowAux[row] if non-null
//        1 = fp16 out
//        2 = fp16 exp(scale*acc) out + atomicAdd fp32 row sums into rowAux
// ---------------------------------------------------------------------------
constexpr int BM = 128, BN = 128, BK = 64, STAGES = 3;
constexpr int STAGE_BYTES = (BM + BN) * BK * 2;            // 32768
constexpr int SMEM_TOTAL  = STAGES * STAGE_BYTES;          // 98304

__device__ __forceinline__ uint32_t swz_addr(uint32_t base, int r, int khalf) {
    int chunk = khalf >> 3;
    return base + r * 128 + (uint32_t)((chunk ^ (r & 7)) << 4);
}

template <int OMODE>
__global__ void __launch_bounds__(256, 2)
gemm_mma(const __half* __restrict__ Ag, const __half* __restrict__ Bg,
         void* __restrict__ Cg,
         int kTiles, int lda, int ldb, int ldc, float scale,
         float* __restrict__ rowAux)
{
    extern __shared__ __align__(1024) char smem[];
    const uint32_t sb = smem_u32(smem);
    const int tid  = threadIdx.x;
    const int wid  = tid >> 5;
    const int lane = tid & 31;
    const int bm = blockIdx.y * BM;
    const int bn = blockIdx.x * BN;
    const int warpM = wid & 1;
    const int warpN = wid >> 1;

    const __half* A = Ag;
    const __half* B = Bg;

    auto load_stage = [&](int s, int k0) {
        uint32_t abase = sb + s * STAGE_BYTES;
        uint32_t bbase = abase + BM * BK * 2;
        #pragma unroll
        for (int j = 0; j < 4; j++) {
            int c = tid + j * 256;
            int r = c >> 3, cc = c & 7;
            cp16(abase + r * 128 + (uint32_t)((cc ^ (r & 7)) << 4),
                 &A[(size_t)(bm + r) * lda + k0 + cc * 8]);
        }
        #pragma unroll
        for (int j = 0; j < 4; j++) {
            int c = tid + j * 256;
            int r = c >> 3, cc = c & 7;
            cp16(bbase + r * 128 + (uint32_t)((cc ^ (r & 7)) << 4),
                 &B[(size_t)(bn + r) * ldb + k0 + cc * 8]);
        }
    };

    float acc[4][4][4];
    #pragma unroll
    for (int fm = 0; fm < 4; fm++)
        #pragma unroll
        for (int fn = 0; fn < 4; fn++)
            #pragma unroll
            for (int e = 0; e < 4; e++) acc[fm][fn][e] = 0.0f;

    uint32_t afr[2][4][4], bfr[2][4][2];

    const int a_r  = lane & 15;
    const int a_kh = (lane >> 4) << 3;
    const int b_r  = ((lane >> 4) << 3) + (lane & 7);
    const int b_kh = ((lane >> 3) & 1) << 3;

    auto fetch = [&](int s, int ks, uint32_t af[4][4], uint32_t bf[4][2]) {
        uint32_t abase = sb + s * STAGE_BYTES;
        uint32_t bbase = abase + BM * BK * 2;
        int k0 = ks * 16;
        #pragma unroll
        for (int fm = 0; fm < 4; fm++) {
            uint32_t addr = swz_addr(abase, warpM * 64 + fm * 16 + a_r, k0 + a_kh);
            LDSM4(af[fm][0], af[fm][1], af[fm][2], af[fm][3], addr);
        }
        #pragma unroll
        for (int g = 0; g < 2; g++) {
            uint32_t addr = swz_addr(bbase, warpN * 32 + g * 16 + b_r, k0 + b_kh);
            uint32_t t0, t1, t2, t3;
            LDSM4(t0, t1, t2, t3, addr);
            bf[g * 2 + 0][0] = t0; bf[g * 2 + 0][1] = t1;
            bf[g * 2 + 1][0] = t2; bf[g * 2 + 1][1] = t3;
        }
    };

    load_stage(0, 0);
    cp_commit();
    load_stage(1, BK);
    cp_commit();

    for (int t = 0; t < kTiles; t++) {
        cp_wait1();
        __syncthreads();
        const int s = t % STAGES;

        fetch(s, 0, afr[0], bfr[0]);
        #pragma unroll
        for (int ks = 0; ks < 4; ks++) {
            if (ks < 3) fetch(s, ks + 1, afr[(ks + 1) & 1], bfr[(ks + 1) & 1]);
            const int cur = ks & 1;
            #pragma unroll
            for (int fm = 0; fm < 4; fm++)
                #pragma unroll
                for (int fn = 0; fn < 4; fn++)
                    MMA16816(acc[fm][fn], afr[cur][fm], bfr[cur][fn]);
        }

        if (t + 2 < kTiles) load_stage((t + 2) % STAGES, (t + 2) * BK);
        cp_commit();
    }

    const int er = bm + warpM * 64 + (lane >> 2);
    const int ec = bn + warpN * 32 + ((lane & 3) << 1);
    #pragma unroll
    for (int fm = 0; fm < 4; fm++) {
        const int r0 = er + fm * 16;
        float rs0 = 1.0f, rs1 = 1.0f;
        if (OMODE == 0 && rowAux) {
            rs0 = 1.0f / rowAux[r0];
            rs1 = 1.0f / rowAux[r0 + 8];
        }
        float rowS0 = 0.0f, rowS1 = 0.0f;   // OMODE 2 partial sums
        #pragma unroll
        for (int fn = 0; fn < 4; fn++) {
            int c = ec + fn * 8;
            if (OMODE == 0) {
                float* Cf = (float*)Cg;
                float2 v0, v1;
                v0.x = acc[fm][fn][0] * scale * rs0; v0.y = acc[fm][fn][1] * scale * rs0;
                v1.x = acc[fm][fn][2] * scale * rs1; v1.y = acc[fm][fn][3] * scale * rs1;
                *(float2*)&Cf[(size_t)r0 * ldc + c]       = v0;
                *(float2*)&Cf[(size_t)(r0 + 8) * ldc + c] = v1;
            } else if (OMODE == 1) {
                __half* Ch = (__half*)Cg;
                __half2 h0 = __floats2half2_rn(acc[fm][fn][0] * scale, acc[fm][fn][1] * scale);
                __half2 h1 = __floats2half2_rn(acc[fm][fn][2] * scale, acc[fm][fn][3] * scale);
                *(__half2*)&Ch[(size_t)r0 * ldc + c]       = h0;
                *(__half2*)&Ch[(size_t)(r0 + 8) * ldc + c] = h1;
            } else {
                // OMODE 2: E = exp(scale * acc), fp16; accumulate fp32 row sums
                __half* Ch = (__half*)Cg;
                float e0 = __expf(acc[fm][fn][0] * scale);
                float e1 = __expf(acc[fm][fn][1] * scale);
                float e2 = __expf(acc[fm][fn][2] * scale);
                float e3 = __expf(acc[fm][fn][3] * scale);
                rowS0 += e0 + e1;
                rowS1 += e2 + e3;
                __half2 h0 = __floats2half2_rn(e0, e1);
                __half2 h1 = __floats2half2_rn(e2, e3);
                *(__half2*)&Ch[(size_t)r0 * ldc + c]       = h0;
                *(__half2*)&Ch[(size_t)(r0 + 8) * ldc + c] = h1;
            }
        }
        if (OMODE == 2) {
            // reduce over the 4 lanes of the column quad (lane&3 varies)
            #pragma unroll
            for (int o = 1; o < 4; o <<= 1) {
                rowS0 += __shfl_xor_sync(0xffffffffu, rowS0, o);
                rowS1 += __shfl_xor_sync(0xffffffffu, rowS1, o);
            }
            if ((lane & 3) == 0) {
                atomicAdd(&rowAux[r0],     rowS0);
                atomicAdd(&rowAux[r0 + 8], rowS1);
            }
        }
    }
}

// ---------------------------------------------------------------------------
// fp32 -> fp16 convert (vectorized)
// ---------------------------------------------------------------------------
__global__ void cvt_f2h4(const float4* __restrict__ in, uint2* __restrict__ out, size_t n4) {
    size_t i = (size_t)blockIdx.x * blockDim.x + threadIdx.x;
    size_t stride = (size_t)gridDim.x * blockDim.x;
    for (; i < n4; i += stride) {
        float4 v = in[i];
        __half2 h0 = __floats2half2_rn(v.x, v.y);
        __half2 h1 = __floats2half2_rn(v.z, v.w);
        uint2 o;
        o.x = *(uint32_t*)&h0;
        o.y = *(uint32_t*)&h1;
        out[i] = o;
    }
}

// W slice [D][O] fp32 -> W^T [O][D] fp16
__global__ void transpose_w(const float* __restrict__ W, __half* __restrict__ WT) {
    __shared__ __half tile[32][33];
    const int d0 = blockIdx.y * 32;
    const int o0 = blockIdx.x * 32;
    const int tx = threadIdx.x, ty = threadIdx.y;
    #pragma unroll
    for (int j = 0; j < 32; j += 8)
        tile[ty + j][tx] = __float2half(W[(size_t)(d0 + ty + j) * Oo + o0 + tx]);
    __syncthreads();
    #pragma unroll
    for (int j = 0; j < 32; j += 8)
        WT[(size_t)(o0 + ty + j) * Dd + d0 + tx] = tile[tx][ty + j];
}

// zero fp32 buffer
__global__ void zero_f32(float* __restrict__ p, int n) {
    int i = blockIdx.x * blockDim.x + threadIdx.x;
    if (i < n) p[i] = 0.0f;
}

// ---------------------------------------------------------------------------
// Persistent stream/event handles (handles only — no device memory)
// ---------------------------------------------------------------------------
struct GraphLanes {
    cudaStream_t s0, s1;
    cudaEvent_t evRoot, evM, evX, evWTv, evJ0, evJ1;
    GraphLanes() {
        cudaStreamCreateWithFlags(&s0, cudaStreamNonBlocking);
        cudaStreamCreateWithFlags(&s1, cudaStreamNonBlocking);
        cudaEventCreateWithFlags(&evRoot, cudaEventDisableTiming);
        cudaEventCreateWithFlags(&evM,    cudaEventDisableTiming);
        cudaEventCreateWithFlags(&evX,    cudaEventDisableTiming);
        cudaEventCreateWithFlags(&evWTv,  cudaEventDisableTiming);
        cudaEventCreateWithFlags(&evJ0,   cudaEventDisableTiming);
        cudaEventCreateWithFlags(&evJ1,   cudaEventDisableTiming);
    }
};

// ---------------------------------------------------------------------------
// Launch: 3-lane forked capture, fully per-batch pipelined chains
// ---------------------------------------------------------------------------
extern "C" void kernel_launch(void* const* d_in, const int* in_sizes, int n_in,
                              void* d_out, int out_size)
{
    const float* x = (const float*)d_in[0];
    const float* w = (const float*)d_in[1];
    if (n_in >= 2 && in_sizes[0] == (int)N_W && in_sizes[1] == (int)N_X) {
        const float* t = x; x = w; w = t;
    }

    static GraphLanes L;

    __half *x16, *w16, *wTv, *M2, *y, *vT, *E;
    float *rsum;
    cudaGetSymbolAddress((void**)&x16,  g_x16);
    cudaGetSymbolAddress((void**)&w16,  g_w16);
    cudaGetSymbolAddress((void**)&wTv,  g_wTv);
    cudaGetSymbolAddress((void**)&M2,   g_M2);
    cudaGetSymbolAddress((void**)&y,    g_y);
    cudaGetSymbolAddress((void**)&vT,   g_vT);
    cudaGetSymbolAddress((void**)&E,    g_exp);
    cudaGetSymbolAddress((void**)&rsum, g_rsum);

    cudaFuncSetAttribute(gemm_mma<0>, cudaFuncAttributeMaxDynamicSharedMemorySize, SMEM_TOTAL);
    cudaFuncSetAttribute(gemm_mma<1>, cudaFuncAttributeMaxDynamicSharedMemorySize, SMEM_TOTAL);
    cudaFuncSetAttribute(gemm_mma<2>, cudaFuncAttributeMaxDynamicSharedMemorySize, SMEM_TOTAL);

    cudaStream_t ds = 0;

    // ---- fork ----
    cudaEventRecord(L.evRoot, ds);
    cudaStreamWaitEvent(L.s0, L.evRoot, 0);
    cudaStreamWaitEvent(L.s1, L.evRoot, 0);

    // lane ds: cvt x (DRAM-bound, biggest input)
    cvt_f2h4<<<3072, 256, 0, ds>>>((const float4*)x, (uint2*)x16, N_X / 4);
    cudaEventRecord(L.evX, ds);

    // lane s0: zero row sums; cvt Wq|Wk; M2 = Wk @ Wq^T
    zero_f32<<<(Bb * Ss) / 256, 256, 0, L.s0>>>(rsum, Bb * Ss);
    cvt_f2h4<<<288, 256, 0, L.s0>>>((const float4*)w, (uint2*)w16, (size_t)2 * Dd * Oo / 4);
    {
        dim3 grid(Dd / BN, Dd / BM, 1);
        gemm_mma<1><<<grid, 256, SMEM_TOTAL, L.s0>>>(
            w16 + (size_t)Dd * Oo, w16, M2,
            Oo / BK, Oo, Oo, Dd, 1.0f, nullptr);
    }
    cudaEventRecord(L.evM, L.s0);

    // lane s1: Wv^T
    {
        dim3 grid(Oo / 32, Dd / 32, 1);
        transpose_w<<<grid, dim3(32, 8), 0, L.s1>>>(w + (size_t)2 * Dd * Oo, wTv);
    }
    cudaEventRecord(L.evWTv, L.s1);

    // ---- cross-lane prerequisites: every lane needs x16, M2, wTv (+rsum zero via evM) ----
    cudaStreamWaitEvent(ds,   L.evM, 0);
    cudaStreamWaitEvent(ds,   L.evWTv, 0);
    cudaStreamWaitEvent(L.s0, L.evX, 0);
    cudaStreamWaitEvent(L.s0, L.evWTv, 0);
    cudaStreamWaitEvent(L.s1, L.evX, 0);
    cudaStreamWaitEvent(L.s1, L.evM, 0);

    // ---- fully per-batch chains: Y_b -> Vt_b -> E_b -> AV_b ----
    cudaStream_t lanes[3] = { ds, L.s0, L.s1 };
    for (int b = 0; b < Bb; b++) {
        cudaStream_t q = lanes[b % 3];
        const size_t xoff = (size_t)b * Ss * Dd;
        const size_t soff = (size_t)b * Ss * Ss;
        const size_t voff = (size_t)b * Oo * Ss;
        float* rs = rsum + (size_t)b * Ss;

        // Y_b = X_b @ M2^T   [2048 x 768]
        {
            dim3 grid(Dd / BN, Ss / BM, 1);
            gemm_mma<1><<<grid, 256, SMEM_TOTAL, q>>>(
                x16 + xoff, M2, y + xoff,
                Dd / BK, Dd, Dd, Dd, 1.0f, nullptr);
        }
        // Vt_b = Wv^T @ X_b^T  [768 x 2048]
        {
            dim3 grid(Ss / BN, Oo / BM, 1);
            gemm_mma<1><<<grid, 256, SMEM_TOTAL, q>>>(
                wTv, x16 + xoff, vT + voff,
                Dd / BK, Dd, Dd, Ss, 1.0f, nullptr);
        }
        // E_b = exp(SCALE * Y_b @ X_b^T), rowsums -> rs  [2048 x 2048]
        {
            dim3 grid(Ss / BN, Ss / BM, 1);
            gemm_mma<2><<<grid, 256, SMEM_TOTAL, q>>>(
                y + xoff, x16 + xoff, E + soff,
                Dd / BK, Dd, Dd, Ss, SCALE, rs);
        }
        // out_b = (E_b @ Vt_b^T) / rowsum  [2048 x 768]
        {
            dim3 grid(Oo / BN, Ss / BM, 1);
            gemm_mma<0><<<grid, 256, SMEM_TOTAL, q>>>(
                E + soff, vT + voff,
                (float*)d_out + (size_t)b * Ss * Oo,
                Ss / BK, Ss, Ss, Oo, 1.0f, rs);
        }
    }

    // ---- join ----
    cudaEventRecord(L.evJ0, L.s0);
    cudaEventRecord(L.evJ1, L.s1);
    cudaStreamWaitEvent(ds, L.evJ0, 0);
    cudaStreamWaitEvent(ds, L.evJ1, 0);
}

// round 13
// speedup vs baseline: 1.0108x; 1.0108x over previous
#include <cuda_runtime.h>
#include <cuda_fp16.h>
#include <cstdint>

// Problem shape (fixed by the dataset)
#define Bb 8
#define Ss 2048
#define Dd 768
#define Oo 768
constexpr float SCALE = 0.125f;  // 1/sqrt(64), hardcoded in reference

constexpr size_t N_X   = (size_t)Bb * Ss * Dd;
constexpr size_t N_W   = (size_t)3 * Dd * Oo;
constexpr size_t N_QKV = (size_t)Bb * Ss * Oo;
constexpr size_t N_SC  = (size_t)Bb * Ss * Ss;

// Scratch (static device globals — no runtime allocation)
__device__ __half g_x16[N_X];             // x fp16 [B*S, D]
__device__ __half g_w16[2 * Dd * Oo];     // Wq|Wk fp16 [D, O]
__device__ __half g_wTv[(size_t)Dd * Oo]; // Wv^T fp16 [O, D]
__device__ __half g_M2[(size_t)Dd * Dd];  // M2 = Wk @ Wq^T fp16
__device__ __half g_y[N_QKV];             // Y = X @ M2^T fp16
__device__ __half g_vT[N_QKV];            // V^T fp16 [B][O, S]
__device__ __half g_exp[N_SC];            // E = exp(scores) fp16 (unnormalized)
__device__ float  g_rsum[(size_t)Bb * Ss]; // rowsum(E) fp32 (atomic accum)

// ---------------------------------------------------------------------------
// PTX helpers (base sm_103 ISA: cp.async, ldmatrix, mma.sync)
// ---------------------------------------------------------------------------
__device__ __forceinline__ uint32_t smem_u32(const void* p) {
    return (uint32_t)__cvta_generic_to_shared(p);
}
__device__ __forceinline__ void cp16(uint32_t saddr, const void* gaddr) {
    asm volatile("cp.async.cg.shared.global [%0], [%1], 16;\n" :: "r"(saddr), "l"(gaddr));
}
__device__ __forceinline__ void cp_commit() {
    asm volatile("cp.async.commit_group;\n" ::: "memory");
}
__device__ __forceinline__ void cp_wait1() {
    asm volatile("cp.async.wait_group 1;\n" ::: "memory");
}

#define LDSM4(r0, r1, r2, r3, addr) \
    asm volatile("ldmatrix.sync.aligned.m8n8.x4.shared.b16 {%0,%1,%2,%3}, [%4];" \
                 : "=r"(r0), "=r"(r1), "=r"(r2), "=r"(r3) : "r"(addr))

#define MMA16816(d, a, b) \
    asm volatile("mma.sync.aligned.m16n8k16.row.col.f32.f16.f16.f32 " \
                 "{%0,%1,%2,%3},{%4,%5,%6,%7},{%8,%9},{%0,%1,%2,%3};" \
                 : "+f"((d)[0]), "+f"((d)[1]), "+f"((d)[2]), "+f"((d)[3]) \
                 : "r"((a)[0]), "r"((a)[1]), "r"((a)[2]), "r"((a)[3]), \
                   "r"((b)[0]), "r"((b)[1]))

// ---------------------------------------------------------------------------
// mma.sync GEMM (NT):  C[M,N] = scale * A[M,K] @ B[N,K]^T  (both K-major fp16)
// Round-8 proven geometry: block 128x128x64, 3-stage cp.async, 8 warps (2x4),
// warp tile 64x32, double-buffered fragments, 2 CTAs/SM. blockIdx.z batches.
// OMODE: 0 = fp32 out, divided by rowAux[row] if non-null
//        1 = fp16 out
//        2 = fp16 exp(scale*acc) out + atomicAdd fp32 row sums into rowAux
// ---------------------------------------------------------------------------
constexpr int BM = 128, BN = 128, BK = 64, STAGES = 3;
constexpr int STAGE_BYTES = (BM + BN) * BK * 2;            // 32768
constexpr int SMEM_TOTAL  = STAGES * STAGE_BYTES;          // 98304

__device__ __forceinline__ uint32_t swz_addr(uint32_t base, int r, int khalf) {
    int chunk = khalf >> 3;
    return base + r * 128 + (uint32_t)((chunk ^ (r & 7)) << 4);
}

template <int OMODE>
__global__ void __launch_bounds__(256, 2)
gemm_mma(const __half* __restrict__ Ag, const __half* __restrict__ Bg,
         void* __restrict__ Cg,
         int kTiles, int lda, int ldb, int ldc, float scale,
         size_t aStr, size_t bStr, size_t cStr,
         float* __restrict__ rowAux)
{
    extern __shared__ __align__(1024) char smem[];
    const uint32_t sb = smem_u32(smem);
    const int tid  = threadIdx.x;
    const int wid  = tid >> 5;
    const int lane = tid & 31;
    const int bm = blockIdx.y * BM;
    const int bn = blockIdx.x * BN;
    const int warpM = wid & 1;
    const int warpN = wid >> 1;

    const __half* A = Ag + (size_t)blockIdx.z * aStr;
    const __half* B = Bg + (size_t)blockIdx.z * bStr;

    auto load_stage = [&](int s, int k0) {
        uint32_t abase = sb + s * STAGE_BYTES;
        uint32_t bbase = abase + BM * BK * 2;
        #pragma unroll
        for (int j = 0; j < 4; j++) {
            int c = tid + j * 256;
            int r = c >> 3, cc = c & 7;
            cp16(abase + r * 128 + (uint32_t)((cc ^ (r & 7)) << 4),
                 &A[(size_t)(bm + r) * lda + k0 + cc * 8]);
        }
        #pragma unroll
        for (int j = 0; j < 4; j++) {
            int c = tid + j * 256;
            int r = c >> 3, cc = c & 7;
            cp16(bbase + r * 128 + (uint32_t)((cc ^ (r & 7)) << 4),
                 &B[(size_t)(bn + r) * ldb + k0 + cc * 8]);
        }
    };

    float acc[4][4][4];
    #pragma unroll
    for (int fm = 0; fm < 4; fm++)
        #pragma unroll
        for (int fn = 0; fn < 4; fn++)
            #pragma unroll
            for (int e = 0; e < 4; e++) acc[fm][fn][e] = 0.0f;

    uint32_t afr[2][4][4], bfr[2][4][2];

    const int a_r  = lane & 15;
    const int a_kh = (lane >> 4) << 3;
    const int b_r  = ((lane >> 4) << 3) + (lane & 7);
    const int b_kh = ((lane >> 3) & 1) << 3;

    auto fetch = [&](int s, int ks, uint32_t af[4][4], uint32_t bf[4][2]) {
        uint32_t abase = sb + s * STAGE_BYTES;
        uint32_t bbase = abase + BM * BK * 2;
        int k0 = ks * 16;
        #pragma unroll
        for (int fm = 0; fm < 4; fm++) {
            uint32_t addr = swz_addr(abase, warpM * 64 + fm * 16 + a_r, k0 + a_kh);
            LDSM4(af[fm][0], af[fm][1], af[fm][2], af[fm][3], addr);
        }
        #pragma unroll
        for (int g = 0; g < 2; g++) {
            uint32_t addr = swz_addr(bbase, warpN * 32 + g * 16 + b_r, k0 + b_kh);
            uint32_t t0, t1, t2, t3;
            LDSM4(t0, t1, t2, t3, addr);
            bf[g * 2 + 0][0] = t0; bf[g * 2 + 0][1] = t1;
            bf[g * 2 + 1][0] = t2; bf[g * 2 + 1][1] = t3;
        }
    };

    load_stage(0, 0);
    cp_commit();
    load_stage(1, BK);
    cp_commit();

    for (int t = 0; t < kTiles; t++) {
        cp_wait1();
        __syncthreads();
        const int s = t % STAGES;

        fetch(s, 0, afr[0], bfr[0]);
        #pragma unroll
        for (int ks = 0; ks < 4; ks++) {
            if (ks < 3) fetch(s, ks + 1, afr[(ks + 1) & 1], bfr[(ks + 1) & 1]);
            const int cur = ks & 1;
            #pragma unroll
            for (int fm = 0; fm < 4; fm++)
                #pragma unroll
                for (int fn = 0; fn < 4; fn++)
                    MMA16816(acc[fm][fn], afr[cur][fm], bfr[cur][fn]);
        }

        if (t + 2 < kTiles) load_stage((t + 2) % STAGES, (t + 2) * BK);
        cp_commit();
    }

    const int er = bm + warpM * 64 + (lane >> 2);
    const int ec = bn + warpN * 32 + ((lane & 3) << 1);
    #pragma unroll
    for (int fm = 0; fm < 4; fm++) {
        const int r0 = er + fm * 16;
        float rs0 = 1.0f, rs1 = 1.0f;
        if (OMODE == 0 && rowAux) {
            rs0 = 1.0f / rowAux[r0];
            rs1 = 1.0f / rowAux[r0 + 8];
        }
        float rowS0 = 0.0f, rowS1 = 0.0f;   // OMODE 2 partial sums
        #pragma unroll
        for (int fn = 0; fn < 4; fn++) {
            int c = ec + fn * 8;
            if (OMODE == 0) {
                float* Cf = (float*)Cg + (size_t)blockIdx.z * cStr;
                float2 v0, v1;
                v0.x = acc[fm][fn][0] * scale * rs0; v0.y = acc[fm][fn][1] * scale * rs0;
                v1.x = acc[fm][fn][2] * scale * rs1; v1.y = acc[fm][fn][3] * scale * rs1;
                *(float2*)&Cf[(size_t)r0 * ldc + c]       = v0;
                *(float2*)&Cf[(size_t)(r0 + 8) * ldc + c] = v1;
            } else if (OMODE == 1) {
                __half* Ch = (__half*)Cg + (size_t)blockIdx.z * cStr;
                __half2 h0 = __floats2half2_rn(acc[fm][fn][0] * scale, acc[fm][fn][1] * scale);
                __half2 h1 = __floats2half2_rn(acc[fm][fn][2] * scale, acc[fm][fn][3] * scale);
                *(__half2*)&Ch[(size_t)r0 * ldc + c]       = h0;
                *(__half2*)&Ch[(size_t)(r0 + 8) * ldc + c] = h1;
            } else {
                // OMODE 2: E = exp(scale * acc), fp16; accumulate fp32 row sums
                __half* Ch = (__half*)Cg + (size_t)blockIdx.z * cStr;
                float e0 = __expf(acc[fm][fn][0] * scale);
                float e1 = __expf(acc[fm][fn][1] * scale);
                float e2 = __expf(acc[fm][fn][2] * scale);
                float e3 = __expf(acc[fm][fn][3] * scale);
                rowS0 += e0 + e1;
                rowS1 += e2 + e3;
                __half2 h0 = __floats2half2_rn(e0, e1);
                __half2 h1 = __floats2half2_rn(e2, e3);
                *(__half2*)&Ch[(size_t)r0 * ldc + c]       = h0;
                *(__half2*)&Ch[(size_t)(r0 + 8) * ldc + c] = h1;
            }
        }
        if (OMODE == 2) {
            // reduce over the 4 lanes of the column quad (lane&3 varies)
            #pragma unroll
            for (int o = 1; o < 4; o <<= 1) {
                rowS0 += __shfl_xor_sync(0xffffffffu, rowS0, o);
                rowS1 += __shfl_xor_sync(0xffffffffu, rowS1, o);
            }
            if ((lane & 3) == 0) {
                atomicAdd(&rowAux[r0],     rowS0);
                atomicAdd(&rowAux[r0 + 8], rowS1);
            }
        }
    }
}

// ---------------------------------------------------------------------------
// fp32 -> fp16 convert (vectorized)
// ---------------------------------------------------------------------------
__global__ void cvt_f2h4(const float4* __restrict__ in, uint2* __restrict__ out, size_t n4) {
    size_t i = (size_t)blockIdx.x * blockDim.x + threadIdx.x;
    size_t stride = (size_t)gridDim.x * blockDim.x;
    for (; i < n4; i += stride) {
        float4 v = in[i];
        __half2 h0 = __floats2half2_rn(v.x, v.y);
        __half2 h1 = __floats2half2_rn(v.z, v.w);
        uint2 o;
        o.x = *(uint32_t*)&h0;
        o.y = *(uint32_t*)&h1;
        out[i] = o;
    }
}

// W slice [D][O] fp32 -> W^T [O][D] fp16
__global__ void transpose_w(const float* __restrict__ W, __half* __restrict__ WT) {
    __shared__ __half tile[32][33];
    const int d0 = blockIdx.y * 32;
    const int o0 = blockIdx.x * 32;
    const int tx = threadIdx.x, ty = threadIdx.y;
    #pragma unroll
    for (int j = 0; j < 32; j += 8)
        tile[ty + j][tx] = __float2half(W[(size_t)(d0 + ty + j) * Oo + o0 + tx]);
    __syncthreads();
    #pragma unroll
    for (int j = 0; j < 32; j += 8)
        WT[(size_t)(o0 + ty + j) * Dd + d0 + tx] = tile[tx][ty + j];
}

// zero fp32 buffer
__global__ void zero_f32(float* __restrict__ p, int n) {
    int i = blockIdx.x * blockDim.x + threadIdx.x;
    if (i < n) p[i] = 0.0f;
}

// ---------------------------------------------------------------------------
// Persistent stream/event handles (handles only — no device memory)
// ---------------------------------------------------------------------------
struct GraphLanes {
    cudaStream_t s0, s1;
    cudaEvent_t evRoot, evM, evX, evY, evV, evJ0, evJ1;
    GraphLanes() {
        cudaStreamCreateWithFlags(&s0, cudaStreamNonBlocking);
        cudaStreamCreateWithFlags(&s1, cudaStreamNonBlocking);
        cudaEventCreateWithFlags(&evRoot, cudaEventDisableTiming);
        cudaEventCreateWithFlags(&evM,    cudaEventDisableTiming);
        cudaEventCreateWithFlags(&evX,    cudaEventDisableTiming);
        cudaEventCreateWithFlags(&evY,    cudaEventDisableTiming);
        cudaEventCreateWithFlags(&evV,    cudaEventDisableTiming);
        cudaEventCreateWithFlags(&evJ0,   cudaEventDisableTiming);
        cudaEventCreateWithFlags(&evJ1,   cudaEventDisableTiming);
    }
};

// ---------------------------------------------------------------------------
// Launch: round-11 DAG (full-width Y and V^T) + fused rowsum epilogues
// ---------------------------------------------------------------------------
extern "C" void kernel_launch(void* const* d_in, const int* in_sizes, int n_in,
                              void* d_out, int out_size)
{
    const float* x = (const float*)d_in[0];
    const float* w = (const float*)d_in[1];
    if (n_in >= 2 && in_sizes[0] == (int)N_W && in_sizes[1] == (int)N_X) {
        const float* t = x; x = w; w = t;
    }

    static GraphLanes L;

    __half *x16, *w16, *wTv, *M2, *y, *vT, *E;
    float *rsum;
    cudaGetSymbolAddress((void**)&x16,  g_x16);
    cudaGetSymbolAddress((void**)&w16,  g_w16);
    cudaGetSymbolAddress((void**)&wTv,  g_wTv);
    cudaGetSymbolAddress((void**)&M2,   g_M2);
    cudaGetSymbolAddress((void**)&y,    g_y);
    cudaGetSymbolAddress((void**)&vT,   g_vT);
    cudaGetSymbolAddress((void**)&E,    g_exp);
    cudaGetSymbolAddress((void**)&rsum, g_rsum);

    cudaFuncSetAttribute(gemm_mma<0>, cudaFuncAttributeMaxDynamicSharedMemorySize, SMEM_TOTAL);
    cudaFuncSetAttribute(gemm_mma<1>, cudaFuncAttributeMaxDynamicSharedMemorySize, SMEM_TOTAL);
    cudaFuncSetAttribute(gemm_mma<2>, cudaFuncAttributeMaxDynamicSharedMemorySize, SMEM_TOTAL);

    cudaStream_t ds = 0;

    // ---- fork ----
    cudaEventRecord(L.evRoot, ds);
    cudaStreamWaitEvent(L.s0, L.evRoot, 0);
    cudaStreamWaitEvent(L.s1, L.evRoot, 0);

    // lane ds: cvt x
    cvt_f2h4<<<3072, 256, 0, ds>>>((const float4*)x, (uint2*)x16, N_X / 4);
    cudaEventRecord(L.evX, ds);

    // lane s0: zero row sums; cvt Wq|Wk -> M2 = Wk @ Wq^T
    zero_f32<<<(Bb * Ss) / 256, 256, 0, L.s0>>>(rsum, Bb * Ss);
    cvt_f2h4<<<288, 256, 0, L.s0>>>((const float4*)w, (uint2*)w16, (size_t)2 * Dd * Oo / 4);
    {
        dim3 grid(Dd / BN, Dd / BM, 1);
        gemm_mma<1><<<grid, 256, SMEM_TOTAL, L.s0>>>(
            w16 + (size_t)Dd * Oo, w16, M2,
            Oo / BK, Oo, Oo, Dd, 1.0f, 0, 0, 0, nullptr);
    }
    cudaEventRecord(L.evM, L.s0);

    // lane s1: Wv^T, then full-width V^T projection (needs x16)
    {
        dim3 grid(Oo / 32, Dd / 32, 1);
        transpose_w<<<grid, dim3(32, 8), 0, L.s1>>>(w + (size_t)2 * Dd * Oo, wTv);
    }
    cudaStreamWaitEvent(L.s1, L.evX, 0);
    {
        dim3 grid(Ss / BN, Oo / BM, Bb);
        gemm_mma<1><<<grid, 256, SMEM_TOTAL, L.s1>>>(
            wTv, x16, vT,
            Dd / BK, Dd, Dd, Ss, 1.0f,
            (size_t)0, (size_t)Ss * Dd, (size_t)Oo * Ss, nullptr);
    }
    cudaEventRecord(L.evV, L.s1);

    // lane ds: full-width Y = X @ M2^T
    cudaStreamWaitEvent(ds, L.evM, 0);
    {
        dim3 grid(Dd / BN, (Bb * Ss) / BM, 1);
        gemm_mma<1><<<grid, 256, SMEM_TOTAL, ds>>>(
            x16, M2, y,
            Dd / BK, Dd, Dd, Dd, 1.0f, 0, 0, 0, nullptr);
    }
    cudaEventRecord(L.evY, ds);

    // ---- per-batch attention chains over 3 lanes ----
    // E_b needs Y (evY carries x16, M2, rsum-zero ordering); AV_b needs vT (evV).
    cudaStreamWaitEvent(ds,   L.evV, 0);
    cudaStreamWaitEvent(L.s0, L.evY, 0);
    cudaStreamWaitEvent(L.s0, L.evV, 0);
    cudaStreamWaitEvent(L.s1, L.evY, 0);

    cudaStream_t lanes[3] = { ds, L.s0, L.s1 };
    for (int b = 0; b < Bb; b++) {
        cudaStream_t q = lanes[b % 3];
        const size_t xoff = (size_t)b * Ss * Dd;
        const size_t soff = (size_t)b * Ss * Ss;
        const size_t voff = (size_t)b * Oo * Ss;
        float* rs = rsum + (size_t)b * Ss;

        // E_b = exp(SCALE * Y_b @ X_b^T), rowsums -> rs  [2048 x 2048]
        {
            dim3 grid(Ss / BN, Ss / BM, 1);
            gemm_mma<2><<<grid, 256, SMEM_TOTAL, q>>>(
                y + xoff, x16 + xoff, E + soff,
                Dd / BK, Dd, Dd, Ss, SCALE, 0, 0, 0, rs);
        }
        // out_b = (E_b @ Vt_b^T) / rowsum  [2048 x 768]
        {
            dim3 grid(Oo / BN, Ss / BM, 1);
            gemm_mma<0><<<grid, 256, SMEM_TOTAL, q>>>(
                E + soff, vT + voff,
                (float*)d_out + (size_t)b * Ss * Oo,
                Ss / BK, Ss, Ss, Oo, 1.0f, 0, 0, 0, rs);
        }
    }

    // ---- join ----
    cudaEventRecord(L.evJ0, L.s0);
    cudaEventRecord(L.evJ1, L.s1);
    cudaStreamWaitEvent(ds, L.evJ0, 0);
    cudaStreamWaitEvent(ds, L.evJ1, 0);
}

// round 14
// speedup vs baseline: 1.0333x; 1.0223x over previous
#include <cuda_runtime.h>
#include <cuda_fp16.h>
#include <cstdint>

// Problem shape (fixed by the dataset)
#define Bb 8
#define Ss 2048
#define Dd 768
#define Oo 768
constexpr float SCALE = 0.125f;  // 1/sqrt(64), hardcoded in reference

constexpr size_t N_X   = (size_t)Bb * Ss * Dd;
constexpr size_t N_W   = (size_t)3 * Dd * Oo;
constexpr size_t N_QKV = (size_t)Bb * Ss * Oo;
constexpr size_t N_SC  = (size_t)Bb * Ss * Ss;

// Scratch (static device globals — no runtime allocation)
__device__ __half g_x16[N_X];             // x fp16 [B*S, D]
__device__ __half g_w16[2 * Dd * Oo];     // Wq|Wk fp16 [D, O]
__device__ __half g_wTv[(size_t)Dd * Oo]; // Wv^T fp16 [O, D]
__device__ __half g_M2[(size_t)Dd * Dd];  // M2 = Wk @ Wq^T fp16
__device__ __half g_y[N_QKV];             // Y = X @ M2^T fp16
__device__ __half g_vT[N_QKV];            // V^T fp16 [B][O, S]
__device__ __half g_exp[N_SC];            // E = exp(scores) fp16 (unnormalized)
__device__ float  g_rinv[(size_t)Bb * Ss]; // 1 / rowsum(E)

// ---------------------------------------------------------------------------
// PTX helpers (base sm_103 ISA: cp.async, ldmatrix, mma.sync)
// ---------------------------------------------------------------------------
__device__ __forceinline__ uint32_t smem_u32(const void* p) {
    return (uint32_t)__cvta_generic_to_shared(p);
}
__device__ __forceinline__ void cp16(uint32_t saddr, const void* gaddr) {
    asm volatile("cp.async.cg.shared.global [%0], [%1], 16;\n" :: "r"(saddr), "l"(gaddr));
}
__device__ __forceinline__ void cp_commit() {
    asm volatile("cp.async.commit_group;\n" ::: "memory");
}
__device__ __forceinline__ void cp_wait1() {
    asm volatile("cp.async.wait_group 1;\n" ::: "memory");
}

#define LDSM4(r0, r1, r2, r3, addr) \
    asm volatile("ldmatrix.sync.aligned.m8n8.x4.shared.b16 {%0,%1,%2,%3}, [%4];" \
                 : "=r"(r0), "=r"(r1), "=r"(r2), "=r"(r3) : "r"(addr))

#define MMA16816(d, a, b) \
    asm volatile("mma.sync.aligned.m16n8k16.row.col.f32.f16.f16.f32 " \
                 "{%0,%1,%2,%3},{%4,%5,%6,%7},{%8,%9},{%0,%1,%2,%3};" \
                 : "+f"((d)[0]), "+f"((d)[1]), "+f"((d)[2]), "+f"((d)[3]) \
                 : "r"((a)[0]), "r"((a)[1]), "r"((a)[2]), "r"((a)[3]), \
                   "r"((b)[0]), "r"((b)[1]))

// ---------------------------------------------------------------------------
// mma.sync GEMM (NT):  C[M,N] = scale * A[M,K] @ B[N,K]^T  (both K-major fp16)
// Round-8/11 proven geometry: block 128x128x64, 3-stage cp.async, 8 warps
// (2x4), warp tile 64x32, double-buffered fragments, 2 CTAs/SM.
// OMODE: 0 = fp32 out (optionally * rowScale[row]); 1 = fp16 out;
//        2 = fp16 exp(scale*acc) out.
// ---------------------------------------------------------------------------
constexpr int BM = 128, BN = 128, BK = 64, STAGES = 3;
constexpr int STAGE_BYTES = (BM + BN) * BK * 2;            // 32768
constexpr int SMEM_TOTAL  = STAGES * STAGE_BYTES;          // 98304

__device__ __forceinline__ uint32_t swz_addr(uint32_t base, int r, int khalf) {
    int chunk = khalf >> 3;
    return base + r * 128 + (uint32_t)((chunk ^ (r & 7)) << 4);
}

template <int OMODE>
__global__ void __launch_bounds__(256, 2)
gemm_mma(const __half* __restrict__ Ag, const __half* __restrict__ Bg,
         void* __restrict__ Cg,
         int kTiles, int lda, int ldb, int ldc, float scale,
         size_t aStr, size_t bStr, size_t cStr,
         const float* __restrict__ rowScale)
{
    extern __shared__ __align__(1024) char smem[];
    const uint32_t sb = smem_u32(smem);
    const int tid  = threadIdx.x;
    const int wid  = tid >> 5;
    const int lane = tid & 31;
    const int bm = blockIdx.y * BM;
    const int bn = blockIdx.x * BN;
    const int warpM = wid & 1;
    const int warpN = wid >> 1;

    const __half* A = Ag + (size_t)blockIdx.z * aStr;
    const __half* B = Bg + (size_t)blockIdx.z * bStr;

    auto load_stage = [&](int s, int k0) {
        uint32_t abase = sb + s * STAGE_BYTES;
        uint32_t bbase = abase + BM * BK * 2;
        #pragma unroll
        for (int j = 0; j < 4; j++) {
            int c = tid + j * 256;
            int r = c >> 3, cc = c & 7;
            cp16(abase + r * 128 + (uint32_t)((cc ^ (r & 7)) << 4),
                 &A[(size_t)(bm + r) * lda + k0 + cc * 8]);
        }
        #pragma unroll
        for (int j = 0; j < 4; j++) {
            int c = tid + j * 256;
            int r = c >> 3, cc = c & 7;
            cp16(bbase + r * 128 + (uint32_t)((cc ^ (r & 7)) << 4),
                 &B[(size_t)(bn + r) * ldb + k0 + cc * 8]);
        }
    };

    float acc[4][4][4];
    #pragma unroll
    for (int fm = 0; fm < 4; fm++)
        #pragma unroll
        for (int fn = 0; fn < 4; fn++)
            #pragma unroll
            for (int e = 0; e < 4; e++) acc[fm][fn][e] = 0.0f;

    uint32_t afr[2][4][4], bfr[2][4][2];

    const int a_r  = lane & 15;
    const int a_kh = (lane >> 4) << 3;
    const int b_r  = ((lane >> 4) << 3) + (lane & 7);
    const int b_kh = ((lane >> 3) & 1) << 3;

    auto fetch = [&](int s, int ks, uint32_t af[4][4], uint32_t bf[4][2]) {
        uint32_t abase = sb + s * STAGE_BYTES;
        uint32_t bbase = abase + BM * BK * 2;
        int k0 = ks * 16;
        #pragma unroll
        for (int fm = 0; fm < 4; fm++) {
            uint32_t addr = swz_addr(abase, warpM * 64 + fm * 16 + a_r, k0 + a_kh);
            LDSM4(af[fm][0], af[fm][1], af[fm][2], af[fm][3], addr);
        }
        #pragma unroll
        for (int g = 0; g < 2; g++) {
            uint32_t addr = swz_addr(bbase, warpN * 32 + g * 16 + b_r, k0 + b_kh);
            uint32_t t0, t1, t2, t3;
            LDSM4(t0, t1, t2, t3, addr);
            bf[g * 2 + 0][0] = t0; bf[g * 2 + 0][1] = t1;
            bf[g * 2 + 1][0] = t2; bf[g * 2 + 1][1] = t3;
        }
    };

    load_stage(0, 0);
    cp_commit();
    load_stage(1, BK);
    cp_commit();

    for (int t = 0; t < kTiles; t++) {
        cp_wait1();
        __syncthreads();
        const int s = t % STAGES;

        fetch(s, 0, afr[0], bfr[0]);
        #pragma unroll
        for (int ks = 0; ks < 4; ks++) {
            if (ks < 3) fetch(s, ks + 1, afr[(ks + 1) & 1], bfr[(ks + 1) & 1]);
            const int cur = ks & 1;
            #pragma unroll
            for (int fm = 0; fm < 4; fm++)
                #pragma unroll
                for (int fn = 0; fn < 4; fn++)
                    MMA16816(acc[fm][fn], afr[cur][fm], bfr[cur][fn]);
        }

        if (t + 2 < kTiles) load_stage((t + 2) % STAGES, (t + 2) * BK);
        cp_commit();
    }

    const int er = bm + warpM * 64 + (lane >> 2);
    const int ec = bn + warpN * 32 + ((lane & 3) << 1);
    #pragma unroll
    for (int fm = 0; fm < 4; fm++) {
        float rs0 = 1.0f, rs1 = 1.0f;
        if (OMODE == 0 && rowScale) {
            rs0 = rowScale[er + fm * 16];
            rs1 = rowScale[er + fm * 16 + 8];
        }
        #pragma unroll
        for (int fn = 0; fn < 4; fn++) {
            int r = er + fm * 16;
            int c = ec + fn * 8;
            if (OMODE == 0) {
                float* Cf = (float*)Cg + (size_t)blockIdx.z * cStr;
                float2 v0, v1;
                v0.x = acc[fm][fn][0] * scale * rs0; v0.y = acc[fm][fn][1] * scale * rs0;
                v1.x = acc[fm][fn][2] * scale * rs1; v1.y = acc[fm][fn][3] * scale * rs1;
                *(float2*)&Cf[(size_t)r * ldc + c]       = v0;
                *(float2*)&Cf[(size_t)(r + 8) * ldc + c] = v1;
            } else if (OMODE == 1) {
                __half* Ch = (__half*)Cg + (size_t)blockIdx.z * cStr;
                __half2 h0 = __floats2half2_rn(acc[fm][fn][0] * scale, acc[fm][fn][1] * scale);
                __half2 h1 = __floats2half2_rn(acc[fm][fn][2] * scale, acc[fm][fn][3] * scale);
                *(__half2*)&Ch[(size_t)r * ldc + c]       = h0;
                *(__half2*)&Ch[(size_t)(r + 8) * ldc + c] = h1;
            } else {
                // OMODE == 2: E = exp(scale * acc), fp16 (safe: |scale*acc| < ~7)
                __half* Ch = (__half*)Cg + (size_t)blockIdx.z * cStr;
                __half2 h0 = __floats2half2_rn(__expf(acc[fm][fn][0] * scale),
                                               __expf(acc[fm][fn][1] * scale));
                __half2 h1 = __floats2half2_rn(__expf(acc[fm][fn][2] * scale),
                                               __expf(acc[fm][fn][3] * scale));
                *(__half2*)&Ch[(size_t)r * ldc + c]       = h0;
                *(__half2*)&Ch[(size_t)(r + 8) * ldc + c] = h1;
            }
        }
    }
}

// ---------------------------------------------------------------------------
// fp32 -> fp16 convert (vectorized)
// ---------------------------------------------------------------------------
__global__ void cvt_f2h4(const float4* __restrict__ in, uint2* __restrict__ out, size_t n4) {
    size_t i = (size_t)blockIdx.x * blockDim.x + threadIdx.x;
    size_t stride = (size_t)gridDim.x * blockDim.x;
    for (; i < n4; i += stride) {
        float4 v = in[i];
        __half2 h0 = __floats2half2_rn(v.x, v.y);
        __half2 h1 = __floats2half2_rn(v.z, v.w);
        uint2 o;
        o.x = *(uint32_t*)&h0;
        o.y = *(uint32_t*)&h1;
        out[i] = o;
    }
}

// W slice [D][O] fp32 -> W^T [O][D] fp16
__global__ void transpose_w(const float* __restrict__ W, __half* __restrict__ WT) {
    __shared__ __half tile[32][33];
    const int d0 = blockIdx.y * 32;
    const int o0 = blockIdx.x * 32;
    const int tx = threadIdx.x, ty = threadIdx.y;
    #pragma unroll
    for (int j = 0; j < 32; j += 8)
        tile[ty + j][tx] = __float2half(W[(size_t)(d0 + ty + j) * Oo + o0 + tx]);
    __syncthreads();
    #pragma unroll
    for (int j = 0; j < 32; j += 8)
        WT[(size_t)(o0 + ty + j) * Dd + d0 + tx] = tile[tx][ty + j];
}

// ---------------------------------------------------------------------------
// Row-sum of E (fp16) -> inv[row] = 1 / sum  (one block per row)
// ---------------------------------------------------------------------------
__device__ __forceinline__ float warpSum(float v) {
    #pragma unroll
    for (int o = 16; o; o >>= 1) v += __shfl_xor_sync(0xffffffffu, v, o);
    return v;
}

__global__ void __launch_bounds__(256)
rowsum_inv(const __half* __restrict__ e, float* __restrict__ inv)
{
    const size_t row = blockIdx.x;
    const uint4* er = (const uint4*)(e + row * Ss);
    const int tid = threadIdx.x;
    const int warp = tid >> 5, lane = tid & 31;

    uint4 u = er[tid];                 // 8 halves per thread * 256 = 2048
    float2 f0 = __half22float2(*(__half2*)&u.x);
    float2 f1 = __half22float2(*(__half2*)&u.y);
    float2 f2 = __half22float2(*(__half2*)&u.z);
    float2 f3 = __half22float2(*(__half2*)&u.w);
    float sum = (f0.x + f0.y) + (f1.x + f1.y) + (f2.x + f2.y) + (f3.x + f3.y);

    __shared__ float red[8];
    sum = warpSum(sum);
    if (lane == 0) red[warp] = sum;
    __syncthreads();
    if (tid == 0) {
        float tot = 0.0f;
        #pragma unroll
        for (int i = 0; i < 8; i++) tot += red[i];
        inv[row] = 1.0f / tot;
    }
}

// ---------------------------------------------------------------------------
// Persistent stream/event handles (handles only — no device memory)
// ---------------------------------------------------------------------------
struct GraphLanes {
    cudaStream_t s0, s1;
    cudaEvent_t evRoot, evM, evX, evY, evV, evJ0, evJ1;
    GraphLanes() {
        cudaStreamCreateWithFlags(&s0, cudaStreamNonBlocking);
        cudaStreamCreateWithFlags(&s1, cudaStreamNonBlocking);
        cudaEventCreateWithFlags(&evRoot, cudaEventDisableTiming);
        cudaEventCreateWithFlags(&evM,    cudaEventDisableTiming);
        cudaEventCreateWithFlags(&evX,    cudaEventDisableTiming);
        cudaEventCreateWithFlags(&evY,    cudaEventDisableTiming);
        cudaEventCreateWithFlags(&evV,    cudaEventDisableTiming);
        cudaEventCreateWithFlags(&evJ0,   cudaEventDisableTiming);
        cudaEventCreateWithFlags(&evJ1,   cudaEventDisableTiming);
    }
};

// ---------------------------------------------------------------------------
// Launch: round-11 DAG exactly; only the chain->lane map is rebalanced
// (ds carries Y + cvt_x, so it gets 2 chains; s0/s1 get 3 each).
// ---------------------------------------------------------------------------
extern "C" void kernel_launch(void* const* d_in, const int* in_sizes, int n_in,
                              void* d_out, int out_size)
{
    const float* x = (const float*)d_in[0];
    const float* w = (const float*)d_in[1];
    if (n_in >= 2 && in_sizes[0] == (int)N_W && in_sizes[1] == (int)N_X) {
        const float* t = x; x = w; w = t;
    }

    static GraphLanes L;

    __half *x16, *w16, *wTv, *M2, *y, *vT, *E;
    float *rinv;
    cudaGetSymbolAddress((void**)&x16,  g_x16);
    cudaGetSymbolAddress((void**)&w16,  g_w16);
    cudaGetSymbolAddress((void**)&wTv,  g_wTv);
    cudaGetSymbolAddress((void**)&M2,   g_M2);
    cudaGetSymbolAddress((void**)&y,    g_y);
    cudaGetSymbolAddress((void**)&vT,   g_vT);
    cudaGetSymbolAddress((void**)&E,    g_exp);
    cudaGetSymbolAddress((void**)&rinv, g_rinv);

    cudaFuncSetAttribute(gemm_mma<0>, cudaFuncAttributeMaxDynamicSharedMemorySize, SMEM_TOTAL);
    cudaFuncSetAttribute(gemm_mma<1>, cudaFuncAttributeMaxDynamicSharedMemorySize, SMEM_TOTAL);
    cudaFuncSetAttribute(gemm_mma<2>, cudaFuncAttributeMaxDynamicSharedMemorySize, SMEM_TOTAL);

    cudaStream_t ds = 0;

    // ---- fork ----
    cudaEventRecord(L.evRoot, ds);
    cudaStreamWaitEvent(L.s0, L.evRoot, 0);
    cudaStreamWaitEvent(L.s1, L.evRoot, 0);

    // lane ds: cvt x
    cvt_f2h4<<<3072, 256, 0, ds>>>((const float4*)x, (uint2*)x16, N_X / 4);
    cudaEventRecord(L.evX, ds);

    // lane s0: cvt Wq|Wk -> M2 = Wk @ Wq^T
    cvt_f2h4<<<288, 256, 0, L.s0>>>((const float4*)w, (uint2*)w16, (size_t)2 * Dd * Oo / 4);
    {
        dim3 grid(Dd / BN, Dd / BM, 1);
        gemm_mma<1><<<grid, 256, SMEM_TOTAL, L.s0>>>(
            w16 + (size_t)Dd * Oo, w16, M2,
            Oo / BK, Oo, Oo, Dd, 1.0f, 0, 0, 0, nullptr);
    }
    cudaEventRecord(L.evM, L.s0);

    // lane s1: Wv^T, then full-width V^T projection (needs x16)
    {
        dim3 grid(Oo / 32, Dd / 32, 1);
        transpose_w<<<grid, dim3(32, 8), 0, L.s1>>>(w + (size_t)2 * Dd * Oo, wTv);
    }
    cudaStreamWaitEvent(L.s1, L.evX, 0);
    {
        dim3 grid(Ss / BN, Oo / BM, Bb);
        gemm_mma<1><<<grid, 256, SMEM_TOTAL, L.s1>>>(
            wTv, x16, vT,
            Dd / BK, Dd, Dd, Ss, 1.0f,
            (size_t)0, (size_t)Ss * Dd, (size_t)Oo * Ss, nullptr);
    }
    cudaEventRecord(L.evV, L.s1);

    // lane ds: full-width Y = X @ M2^T
    cudaStreamWaitEvent(ds, L.evM, 0);
    {
        dim3 grid(Dd / BN, (Bb * Ss) / BM, 1);
        gemm_mma<1><<<grid, 256, SMEM_TOTAL, ds>>>(
            x16, M2, y,
            Dd / BK, Dd, Dd, Dd, 1.0f, 0, 0, 0, nullptr);
    }
    cudaEventRecord(L.evY, ds);

    // ---- per-batch attention chains, rebalanced over 3 lanes ----
    cudaStreamWaitEvent(ds,   L.evV, 0);
    cudaStreamWaitEvent(L.s0, L.evY, 0);
    cudaStreamWaitEvent(L.s0, L.evV, 0);
    cudaStreamWaitEvent(L.s1, L.evY, 0);

    // ds (heaviest prework): 2 chains; s0: 3; s1: 3
    cudaStream_t laneOf[Bb] = { L.s0, L.s1, ds, L.s0, L.s1, ds, L.s0, L.s1 };

    for (int b = 0; b < Bb; b++) {
        cudaStream_t q = laneOf[b];
        const size_t xoff = (size_t)b * Ss * Dd;
        const size_t soff = (size_t)b * Ss * Ss;

        // E_b = exp( SCALE * Y_b @ X_b^T )  (fp16, unnormalized)
        {
            dim3 grid(Ss / BN, Ss / BM, 1);
            gemm_mma<2><<<grid, 256, SMEM_TOTAL, q>>>(
                y + xoff, x16 + xoff, E + soff,
                Dd / BK, Dd, Dd, Ss, SCALE, 0, 0, 0, nullptr);
        }
        // inv rowsum
        rowsum_inv<<<Ss, 256, 0, q>>>(E + soff, rinv + (size_t)b * Ss);
        // out_b = diag(rinv) * (E_b @ (V^T_b)^T)
        {
            dim3 grid(Oo / BN, Ss / BM, 1);
            gemm_mma<0><<<grid, 256, SMEM_TOTAL, q>>>(
                E + soff, vT + (size_t)b * Oo * Ss,
                (float*)d_out + (size_t)b * Ss * Oo,
                Ss / BK, Ss, Ss, Oo, 1.0f, 0, 0, 0,
                rinv + (size_t)b * Ss);
        }
    }

    // ---- join ----
    cudaEventRecord(L.evJ0, L.s0);
    cudaEventRecord(L.evJ1, L.s1);
    cudaStreamWaitEvent(ds, L.evJ0, 0);
    cudaStreamWaitEvent(ds, L.evJ1, 0);
}

// round 15
// speedup vs baseline: 1.0953x; 1.0600x over previous
#include <cuda_runtime.h>
#include <cuda_fp16.h>
#include <cstdint>

// Problem shape (fixed by the dataset)
#define Bb 8
#define Ss 2048
#define Dd 768
#define Oo 768
constexpr float SCALE = 0.125f;  // 1/sqrt(64), hardcoded in reference

constexpr size_t N_X   = (size_t)Bb * Ss * Dd;
constexpr size_t N_W   = (size_t)3 * Dd * Oo;
constexpr size_t N_QKV = (size_t)Bb * Ss * Oo;
constexpr size_t N_SC  = (size_t)Bb * Ss * Ss;
constexpr size_t X_HALF = N_X / 2;                 // 4 batches of x

// Scratch (static device globals — no runtime allocation)
__device__ __half g_x16[N_X];             // x fp16 [B*S, D]
__device__ __half g_w16[2 * Dd * Oo];     // Wq|Wk fp16 [D, O]
__device__ __half g_wTv[(size_t)Dd * Oo]; // Wv^T fp16 [O, D]
__device__ __half g_M2[(size_t)Dd * Dd];  // M2 = Wk @ Wq^T fp16
__device__ __half g_y[N_QKV];             // Y = X @ M2^T fp16
__device__ __half g_vT[N_QKV];            // V^T fp16 [B][O, S]
__device__ __half g_exp[N_SC];            // E = exp(scores) fp16 (unnormalized)
__device__ float  g_rinv[(size_t)Bb * Ss]; // 1 / rowsum(E)

// ---------------------------------------------------------------------------
// PTX helpers (base sm_103 ISA: cp.async, ldmatrix, mma.sync)
// ---------------------------------------------------------------------------
__device__ __forceinline__ uint32_t smem_u32(const void* p) {
    return (uint32_t)__cvta_generic_to_shared(p);
}
__device__ __forceinline__ void cp16(uint32_t saddr, const void* gaddr) {
    asm volatile("cp.async.cg.shared.global [%0], [%1], 16;\n" :: "r"(saddr), "l"(gaddr));
}
__device__ __forceinline__ void cp_commit() {
    asm volatile("cp.async.commit_group;\n" ::: "memory");
}
__device__ __forceinline__ void cp_wait1() {
    asm volatile("cp.async.wait_group 1;\n" ::: "memory");
}

#define LDSM4(r0, r1, r2, r3, addr) \
    asm volatile("ldmatrix.sync.aligned.m8n8.x4.shared.b16 {%0,%1,%2,%3}, [%4];" \
                 : "=r"(r0), "=r"(r1), "=r"(r2), "=r"(r3) : "r"(addr))

#define MMA16816(d, a, b) \
    asm volatile("mma.sync.aligned.m16n8k16.row.col.f32.f16.f16.f32 " \
                 "{%0,%1,%2,%3},{%4,%5,%6,%7},{%8,%9},{%0,%1,%2,%3};" \
                 : "+f"((d)[0]), "+f"((d)[1]), "+f"((d)[2]), "+f"((d)[3]) \
                 : "r"((a)[0]), "r"((a)[1]), "r"((a)[2]), "r"((a)[3]), \
                   "r"((b)[0]), "r"((b)[1]))

// ---------------------------------------------------------------------------
// mma.sync GEMM (NT):  C[M,N] = scale * A[M,K] @ B[N,K]^T  (both K-major fp16)
// Proven geometry: block 128x128x64, 3-stage cp.async, 8 warps (2x4),
// warp tile 64x32, double-buffered fragments, 2 CTAs/SM.
// OMODE: 0 = fp32 out (optionally * rowScale[row]); 1 = fp16 out;
//        2 = fp16 exp(scale*acc) out.
// ---------------------------------------------------------------------------
constexpr int BM = 128, BN = 128, BK = 64, STAGES = 3;
constexpr int STAGE_BYTES = (BM + BN) * BK * 2;            // 32768
constexpr int SMEM_TOTAL  = STAGES * STAGE_BYTES;          // 98304

__device__ __forceinline__ uint32_t swz_addr(uint32_t base, int r, int khalf) {
    int chunk = khalf >> 3;
    return base + r * 128 + (uint32_t)((chunk ^ (r & 7)) << 4);
}

template <int OMODE>
__global__ void __launch_bounds__(256, 2)
gemm_mma(const __half* __restrict__ Ag, const __half* __restrict__ Bg,
         void* __restrict__ Cg,
         int kTiles, int lda, int ldb, int ldc, float scale,
         size_t aStr, size_t bStr, size_t cStr,
         const float* __restrict__ rowScale)
{
    extern __shared__ __align__(1024) char smem[];
    const uint32_t sb = smem_u32(smem);
    const int tid  = threadIdx.x;
    const int wid  = tid >> 5;
    const int lane = tid & 31;
    const int bm = blockIdx.y * BM;
    const int bn = blockIdx.x * BN;
    const int warpM = wid & 1;
    const int warpN = wid >> 1;

    const __half* A = Ag + (size_t)blockIdx.z * aStr;
    const __half* B = Bg + (size_t)blockIdx.z * bStr;

    auto load_stage = [&](int s, int k0) {
        uint32_t abase = sb + s * STAGE_BYTES;
        uint32_t bbase = abase + BM * BK * 2;
        #pragma unroll
        for (int j = 0; j < 4; j++) {
            int c = tid + j * 256;
            int r = c >> 3, cc = c & 7;
            cp16(abase + r * 128 + (uint32_t)((cc ^ (r & 7)) << 4),
                 &A[(size_t)(bm + r) * lda + k0 + cc * 8]);
        }
        #pragma unroll
        for (int j = 0; j < 4; j++) {
            int c = tid + j * 256;
            int r = c >> 3, cc = c & 7;
            cp16(bbase + r * 128 + (uint32_t)((cc ^ (r & 7)) << 4),
                 &B[(size_t)(bn + r) * ldb + k0 + cc * 8]);
        }
    };

    float acc[4][4][4];
    #pragma unroll
    for (int fm = 0; fm < 4; fm++)
        #pragma unroll
        for (int fn = 0; fn < 4; fn++)
            #pragma unroll
            for (int e = 0; e < 4; e++) acc[fm][fn][e] = 0.0f;

    uint32_t afr[2][4][4], bfr[2][4][2];

    const int a_r  = lane & 15;
    const int a_kh = (lane >> 4) << 3;
    const int b_r  = ((lane >> 4) << 3) + (lane & 7);
    const int b_kh = ((lane >> 3) & 1) << 3;

    auto fetch = [&](int s, int ks, uint32_t af[4][4], uint32_t bf[4][2]) {
        uint32_t abase = sb + s * STAGE_BYTES;
        uint32_t bbase = abase + BM * BK * 2;
        int k0 = ks * 16;
        #pragma unroll
        for (int fm = 0; fm < 4; fm++) {
            uint32_t addr = swz_addr(abase, warpM * 64 + fm * 16 + a_r, k0 + a_kh);
            LDSM4(af[fm][0], af[fm][1], af[fm][2], af[fm][3], addr);
        }
        #pragma unroll
        for (int g = 0; g < 2; g++) {
            uint32_t addr = swz_addr(bbase, warpN * 32 + g * 16 + b_r, k0 + b_kh);
            uint32_t t0, t1, t2, t3;
            LDSM4(t0, t1, t2, t3, addr);
            bf[g * 2 + 0][0] = t0; bf[g * 2 + 0][1] = t1;
            bf[g * 2 + 1][0] = t2; bf[g * 2 + 1][1] = t3;
        }
    };

    load_stage(0, 0);
    cp_commit();
    load_stage(1, BK);
    cp_commit();

    for (int t = 0; t < kTiles; t++) {
        cp_wait1();
        __syncthreads();
        const int s = t % STAGES;

        fetch(s, 0, afr[0], bfr[0]);
        #pragma unroll
        for (int ks = 0; ks < 4; ks++) {
            if (ks < 3) fetch(s, ks + 1, afr[(ks + 1) & 1], bfr[(ks + 1) & 1]);
            const int cur = ks & 1;
            #pragma unroll
            for (int fm = 0; fm < 4; fm++)
                #pragma unroll
                for (int fn = 0; fn < 4; fn++)
                    MMA16816(acc[fm][fn], afr[cur][fm], bfr[cur][fn]);
        }

        if (t + 2 < kTiles) load_stage((t + 2) % STAGES, (t + 2) * BK);
        cp_commit();
    }

    const int er = bm + warpM * 64 + (lane >> 2);
    const int ec = bn + warpN * 32 + ((lane & 3) << 1);
    #pragma unroll
    for (int fm = 0; fm < 4; fm++) {
        float rs0 = 1.0f, rs1 = 1.0f;
        if (OMODE == 0 && rowScale) {
            rs0 = rowScale[er + fm * 16];
            rs1 = rowScale[er + fm * 16 + 8];
        }
        #pragma unroll
        for (int fn = 0; fn < 4; fn++) {
            int r = er + fm * 16;
            int c = ec + fn * 8;
            if (OMODE == 0) {
                float* Cf = (float*)Cg + (size_t)blockIdx.z * cStr;
                float2 v0, v1;
                v0.x = acc[fm][fn][0] * scale * rs0; v0.y = acc[fm][fn][1] * scale * rs0;
                v1.x = acc[fm][fn][2] * scale * rs1; v1.y = acc[fm][fn][3] * scale * rs1;
                *(float2*)&Cf[(size_t)r * ldc + c]       = v0;
                *(float2*)&Cf[(size_t)(r + 8) * ldc + c] = v1;
            } else if (OMODE == 1) {
                __half* Ch = (__half*)Cg + (size_t)blockIdx.z * cStr;
                __half2 h0 = __floats2half2_rn(acc[fm][fn][0] * scale, acc[fm][fn][1] * scale);
                __half2 h1 = __floats2half2_rn(acc[fm][fn][2] * scale, acc[fm][fn][3] * scale);
                *(__half2*)&Ch[(size_t)r * ldc + c]       = h0;
                *(__half2*)&Ch[(size_t)(r + 8) * ldc + c] = h1;
            } else {
                __half* Ch = (__half*)Cg + (size_t)blockIdx.z * cStr;
                __half2 h0 = __floats2half2_rn(__expf(acc[fm][fn][0] * scale),
                                               __expf(acc[fm][fn][1] * scale));
                __half2 h1 = __floats2half2_rn(__expf(acc[fm][fn][2] * scale),
                                               __expf(acc[fm][fn][3] * scale));
                *(__half2*)&Ch[(size_t)r * ldc + c]       = h0;
                *(__half2*)&Ch[(size_t)(r + 8) * ldc + c] = h1;
            }
        }
    }
}

// ---------------------------------------------------------------------------
// fp32 -> fp16 convert (vectorized)
// ---------------------------------------------------------------------------
__global__ void cvt_f2h4(const float4* __restrict__ in, uint2* __restrict__ out, size_t n4) {
    size_t i = (size_t)blockIdx.x * blockDim.x + threadIdx.x;
    size_t stride = (size_t)gridDim.x * blockDim.x;
    for (; i < n4; i += stride) {
        float4 v = in[i];
        __half2 h0 = __floats2half2_rn(v.x, v.y);
        __half2 h1 = __floats2half2_rn(v.z, v.w);
        uint2 o;
        o.x = *(uint32_t*)&h0;
        o.y = *(uint32_t*)&h1;
        out[i] = o;
    }
}

// W slice [D][O] fp32 -> W^T [O][D] fp16
__global__ void transpose_w(const float* __restrict__ W, __half* __restrict__ WT) {
    __shared__ __half tile[32][33];
    const int d0 = blockIdx.y * 32;
    const int o0 = blockIdx.x * 32;
    const int tx = threadIdx.x, ty = threadIdx.y;
    #pragma unroll
    for (int j = 0; j < 32; j += 8)
        tile[ty + j][tx] = __float2half(W[(size_t)(d0 + ty + j) * Oo + o0 + tx]);
    __syncthreads();
    #pragma unroll
    for (int j = 0; j < 32; j += 8)
        WT[(size_t)(o0 + ty + j) * Dd + d0 + tx] = tile[tx][ty + j];
}

// ---------------------------------------------------------------------------
// Row-sum of E (fp16) -> inv[row] = 1 / sum  (one block per row)
// ---------------------------------------------------------------------------
__device__ __forceinline__ float warpSum(float v) {
    #pragma unroll
    for (int o = 16; o; o >>= 1) v += __shfl_xor_sync(0xffffffffu, v, o);
    return v;
}

__global__ void __launch_bounds__(256)
rowsum_inv(const __half* __restrict__ e, float* __restrict__ inv)
{
    const size_t row = blockIdx.x;
    const uint4* er = (const uint4*)(e + row * Ss);
    const int tid = threadIdx.x;
    const int warp = tid >> 5, lane = tid & 31;

    uint4 u = er[tid];
    float2 f0 = __half22float2(*(__half2*)&u.x);
    float2 f1 = __half22float2(*(__half2*)&u.y);
    float2 f2 = __half22float2(*(__half2*)&u.z);
    float2 f3 = __half22float2(*(__half2*)&u.w);
    float sum = (f0.x + f0.y) + (f1.x + f1.y) + (f2.x + f2.y) + (f3.x + f3.y);

    __shared__ float red[8];
    sum = warpSum(sum);
    if (lane == 0) red[warp] = sum;
    __syncthreads();
    if (tid == 0) {
        float tot = 0.0f;
        #pragma unroll
        for (int i = 0; i < 8; i++) tot += red[i];
        inv[row] = 1.0f / tot;
    }
}

// ---------------------------------------------------------------------------
// Persistent stream/event handles (handles only — no device memory)
// ---------------------------------------------------------------------------
struct GraphLanes {
    cudaStream_t s0, s1;
    cudaEvent_t evRoot, evM, evX0, evX1, evY0, evY1, evV0, evV1, evJ0, evJ1;
    GraphLanes() {
        cudaStreamCreateWithFlags(&s0, cudaStreamNonBlocking);
        cudaStreamCreateWithFlags(&s1, cudaStreamNonBlocking);
        cudaEventCreateWithFlags(&evRoot, cudaEventDisableTiming);
        cudaEventCreateWithFlags(&evM,    cudaEventDisableTiming);
        cudaEventCreateWithFlags(&evX0,   cudaEventDisableTiming);
        cudaEventCreateWithFlags(&evX1,   cudaEventDisableTiming);
        cudaEventCreateWithFlags(&evY0,   cudaEventDisableTiming);
        cudaEventCreateWithFlags(&evY1,   cudaEventDisableTiming);
        cudaEventCreateWithFlags(&evV0,   cudaEventDisableTiming);
        cudaEventCreateWithFlags(&evV1,   cudaEventDisableTiming);
        cudaEventCreateWithFlags(&evJ0,   cudaEventDisableTiming);
        cudaEventCreateWithFlags(&evJ1,   cudaEventDisableTiming);
    }
};

// ---------------------------------------------------------------------------
// Launch: half-granularity pipelined front-end + per-batch chains
//   H0 = batches 0-3, H1 = batches 4-7.
//   ds: cvtH0 -> Y_H0 -> Y_H1 -> chains {2, 5}
//   s0: cvt_w -> M2 -> cvtH1 -> chains {0, 3, 6}
//   s1: transpose_w -> Vt_H0 -> Vt_H1 -> chains {1, 4, 7}
// ---------------------------------------------------------------------------
extern "C" void kernel_launch(void* const* d_in, const int* in_sizes, int n_in,
                              void* d_out, int out_size)
{
    const float* x = (const float*)d_in[0];
    const float* w = (const float*)d_in[1];
    if (n_in >= 2 && in_sizes[0] == (int)N_W && in_sizes[1] == (int)N_X) {
        const float* t = x; x = w; w = t;
    }

    static GraphLanes L;

    __half *x16, *w16, *wTv, *M2, *y, *vT, *E;
    float *rinv;
    cudaGetSymbolAddress((void**)&x16,  g_x16);
    cudaGetSymbolAddress((void**)&w16,  g_w16);
    cudaGetSymbolAddress((void**)&wTv,  g_wTv);
    cudaGetSymbolAddress((void**)&M2,   g_M2);
    cudaGetSymbolAddress((void**)&y,    g_y);
    cudaGetSymbolAddress((void**)&vT,   g_vT);
    cudaGetSymbolAddress((void**)&E,    g_exp);
    cudaGetSymbolAddress((void**)&rinv, g_rinv);

    cudaFuncSetAttribute(gemm_mma<0>, cudaFuncAttributeMaxDynamicSharedMemorySize, SMEM_TOTAL);
    cudaFuncSetAttribute(gemm_mma<1>, cudaFuncAttributeMaxDynamicSharedMemorySize, SMEM_TOTAL);
    cudaFuncSetAttribute(gemm_mma<2>, cudaFuncAttributeMaxDynamicSharedMemorySize, SMEM_TOTAL);

    cudaStream_t ds = 0;

    // ---- fork ----
    cudaEventRecord(L.evRoot, ds);
    cudaStreamWaitEvent(L.s0, L.evRoot, 0);
    cudaStreamWaitEvent(L.s1, L.evRoot, 0);

    // ds: cvt x first half (batches 0-3)
    cvt_f2h4<<<1536, 256, 0, ds>>>((const float4*)x, (uint2*)x16, X_HALF / 4);
    cudaEventRecord(L.evX0, ds);

    // s0: cvt Wq|Wk -> M2 -> cvt x second half
    cvt_f2h4<<<288, 256, 0, L.s0>>>((const float4*)w, (uint2*)w16, (size_t)2 * Dd * Oo / 4);
    {
        dim3 grid(Dd / BN, Dd / BM, 1);
        gemm_mma<1><<<grid, 256, SMEM_TOTAL, L.s0>>>(
            w16 + (size_t)Dd * Oo, w16, M2,
            Oo / BK, Oo, Oo, Dd, 1.0f, 0, 0, 0, nullptr);
    }
    cudaEventRecord(L.evM, L.s0);
    cvt_f2h4<<<1536, 256, 0, L.s0>>>(
        (const float4*)(x + X_HALF), (uint2*)(x16 + X_HALF), X_HALF / 4);
    cudaEventRecord(L.evX1, L.s0);

    // s1: Wv^T transpose, then Vt halves
    {
        dim3 grid(Oo / 32, Dd / 32, 1);
        transpose_w<<<grid, dim3(32, 8), 0, L.s1>>>(w + (size_t)2 * Dd * Oo, wTv);
    }
    cudaStreamWaitEvent(L.s1, L.evX0, 0);
    {
        dim3 grid(Ss / BN, Oo / BM, 4);   // Vt for batches 0-3
        gemm_mma<1><<<grid, 256, SMEM_TOTAL, L.s1>>>(
            wTv, x16, vT,
            Dd / BK, Dd, Dd, Ss, 1.0f,
            (size_t)0, (size_t)Ss * Dd, (size_t)Oo * Ss, nullptr);
    }
    cudaEventRecord(L.evV0, L.s1);
    cudaStreamWaitEvent(L.s1, L.evX1, 0);
    {
        dim3 grid(Ss / BN, Oo / BM, 4);   // Vt for batches 4-7
        gemm_mma<1><<<grid, 256, SMEM_TOTAL, L.s1>>>(
            wTv, x16 + X_HALF, vT + 4 * (size_t)Oo * Ss,
            Dd / BK, Dd, Dd, Ss, 1.0f,
            (size_t)0, (size_t)Ss * Dd, (size_t)Oo * Ss, nullptr);
    }
    cudaEventRecord(L.evV1, L.s1);

    // ds: Y halves (need M2)
    cudaStreamWaitEvent(ds, L.evM, 0);
    {
        dim3 grid(Dd / BN, 4 * Ss / BM, 1);   // Y for batches 0-3 (M = 4*2048)
        gemm_mma<1><<<grid, 256, SMEM_TOTAL, ds>>>(
            x16, M2, y,
            Dd / BK, Dd, Dd, Dd, 1.0f, 0, 0, 0, nullptr);
    }
    cudaEventRecord(L.evY0, ds);
    cudaStreamWaitEvent(ds, L.evX1, 0);
    {
        dim3 grid(Dd / BN, 4 * Ss / BM, 1);   // Y for batches 4-7
        gemm_mma<1><<<grid, 256, SMEM_TOTAL, ds>>>(
            x16 + X_HALF, M2, y + X_HALF,
            Dd / BK, Dd, Dd, Dd, 1.0f, 0, 0, 0, nullptr);
    }
    cudaEventRecord(L.evY1, ds);

    // ---- per-batch attention chains ----
    auto chain = [&](int b, cudaStream_t q) {
        const size_t xoff = (size_t)b * Ss * Dd;
        const size_t soff = (size_t)b * Ss * Ss;
        {
            dim3 grid(Ss / BN, Ss / BM, 1);
            gemm_mma<2><<<grid, 256, SMEM_TOTAL, q>>>(
                y + xoff, x16 + xoff, E + soff,
                Dd / BK, Dd, Dd, Ss, SCALE, 0, 0, 0, nullptr);
        }
        rowsum_inv<<<Ss, 256, 0, q>>>(E + soff, rinv + (size_t)b * Ss);
        {
            dim3 grid(Oo / BN, Ss / BM, 1);
            gemm_mma<0><<<grid, 256, SMEM_TOTAL, q>>>(
                E + soff, vT + (size_t)b * Oo * Ss,
                (float*)d_out + (size_t)b * Ss * Oo,
                Ss / BK, Ss, Ss, Oo, 1.0f, 0, 0, 0,
                rinv + (size_t)b * Ss);
        }
    };

    // H0 chains: need evY0 + evV0 (each event carries its inputs' ordering)
    cudaStreamWaitEvent(L.s0, L.evY0, 0);
    cudaStreamWaitEvent(L.s0, L.evV0, 0);
    cudaStreamWaitEvent(L.s1, L.evY0, 0);   // evV0 is same-stream on s1
    cudaStreamWaitEvent(ds,   L.evV0, 0);   // evY0 same-stream on ds

    chain(0, L.s0);
    chain(1, L.s1);
    chain(2, ds);
    chain(3, L.s0);

    // H1 chains: need evY1 + evV1
    cudaStreamWaitEvent(L.s0, L.evY1, 0);
    cudaStreamWaitEvent(L.s0, L.evV1, 0);
    cudaStreamWaitEvent(L.s1, L.evY1, 0);   // evV1 same-stream on s1
    cudaStreamWaitEvent(ds,   L.evV1, 0);   // evY1 same-stream on ds

    chain(4, L.s1);
    chain(5, ds);
    chain(6, L.s0);
    chain(7, L.s1);

    // ---- join ----
    cudaEventRecord(L.evJ0, L.s0);
    cudaEventRecord(L.evJ1, L.s1);
    cudaStreamWaitEvent(ds, L.evJ0, 0);
    cudaStreamWaitEvent(ds, L.evJ1, 0);
}